// round 14
// baseline (speedup 1.0000x reference)
#include <cuda_runtime.h>

#define DEVINL __device__ __forceinline__
typedef unsigned long long ull;

constexpr int B = 64, T = 256, W = 20, NP = 6, NT = 12, CC = 32, FD = 8, PROJ = 64;
constexpr int NG = 4 * PROJ;            // 256 gates
constexpr int NWIN = B * T;             // 16384
constexpr int WPB = 16;                 // windows per enc block (2 per warp)
constexpr int NCHUNK = 16;              // t-chunks per batch row
constexpr int NLSTM = 32;               // LSTM blocks (2 rows each)

// scratch
__device__ float g_xg[NWIN * NG];       // 16 MB: xg = feat @ Wih^T + (bih+bhh)
__device__ int   g_flag[B * NCHUNK];    // chunk flags (self-resetting, start 0)

DEVINL void fma2(ull& d, ull a, ull b) {
    asm("fma.rn.f32x2 %0, %1, %2, %0;" : "+l"(d) : "l"(a), "l"(b));
}
DEVINL void add2(ull& d, ull a, ull b) {
    asm("add.rn.f32x2 %0, %1, %2;" : "=l"(d) : "l"(a), "l"(b));
}
DEVINL float hsum2(ull a) {
    float lo, hi;
    asm("mov.b64 {%0,%1}, %2;" : "=f"(lo), "=f"(hi) : "l"(a));
    return lo + hi;
}
DEVINL ull pack2(float lo, float hi) {
    ull r;
    asm("mov.b64 %0, {%1,%2};" : "=l"(r) : "f"(lo), "f"(hi));
    return r;
}
DEVINL void upk(ull a, float& lo, float& hi) {
    asm("mov.b64 {%0,%1}, %2;" : "=f"(lo), "=f"(hi) : "l"(a));
}

DEVINL float sigm(float x) { return __fdividef(1.f, 1.f + __expf(-x)); }
DEVINL float tanh_(float x) { return __fdividef(2.f, 1.f + __expf(-2.f * x)) - 1.f; }

// ---------------------------------------------------------------------------
// smem layout (floats) — dynamic shared (enc role), identical to r10/r12
// ---------------------------------------------------------------------------
constexpr int OFF_W1P  = 0;                       // 576
constexpr int OFF_W1T  = OFF_W1P + 576;           // 1152
constexpr int OFF_W2P  = OFF_W1T + 1152;          // 3072
constexpr int OFF_W2T  = OFF_W2P + 3072;          // 3072
constexpr int OFF_B1P  = OFF_W2T + 3072;          // 32
constexpr int OFF_B1T  = OFF_B1P + 32;            // 32
constexpr int OFF_B2P  = OFF_B1T + 32;            // 32
constexpr int OFF_B2T  = OFF_B2P + 32;            // 32
constexpr int OFF_BIAS = OFF_B2T + 32;            // 256
constexpr int OFF_XP   = OFF_BIAS + 256;          // 8 * 128
constexpr int OFF_XT   = OFF_XP + 8 * 128;        // 8 * 256
constexpr int OFF_H1   = OFF_XT + 8 * 256;        // 8 * 576
constexpr int OFF_CAT  = OFF_H1 + 8 * 576;        // 8 * 80
constexpr int OFF_PRJ  = OFF_CAT + 8 * 80;        // 16 * 64
constexpr int OFF_PRW  = OFF_PRJ + 16 * 64;       // 4608
constexpr int SMEM_FLOATS = OFF_PRW + 4608;
constexpr int SMEM_BYTES = SMEM_FLOATS * 4;       // 88832 B

// ---------------------------------------------------------------------------
// conv helpers (unchanged)
// ---------------------------------------------------------------------------
template <int NPAIR, int STRIDE>
DEVINL void conv1P(const float* __restrict__ s_x, const float* __restrict__ s_w,
                   float bv, float* __restrict__ h1T) {
    ull acc[18];
#pragma unroll
    for (int j = 0; j < 18; j++) acc[j] = 0ull;
#pragma unroll
    for (int m = 0; m < NPAIR; m++) {
        ull w0 = *reinterpret_cast<const ull*>(s_w + (3 * m + 0) * 64);
        ull w1 = *reinterpret_cast<const ull*>(s_w + (3 * m + 1) * 64);
        ull w2 = *reinterpret_cast<const ull*>(s_w + (3 * m + 2) * 64);
#pragma unroll
        for (int j = 0; j < 20; j++) {
            ull v = *reinterpret_cast<const ull*>(s_x + j * STRIDE + 2 * m);
            if (j < 18) fma2(acc[j], v, w0);
            if (j >= 1 && j <= 18) fma2(acc[j - 1], v, w1);
            if (j >= 2) fma2(acc[j - 2], v, w2);
        }
    }
#pragma unroll
    for (int j = 0; j < 18; j++)
        h1T[j * 32] = fmaxf(hsum2(acc[j]) + bv, 0.f);
}

template <int NQUAD, int STRIDE>
DEVINL void conv1Q(const float* __restrict__ s_x, const float* __restrict__ s_w,
                   float bv, float* __restrict__ h1T) {
    ull acc[18];
#pragma unroll
    for (int j = 0; j < 18; j++) acc[j] = 0ull;
#pragma unroll
    for (int mm = 0; mm < NQUAD; mm++) {
        ulonglong2 w0 = *reinterpret_cast<const ulonglong2*>(s_w + (3 * mm + 0) * 128);
        ulonglong2 w1 = *reinterpret_cast<const ulonglong2*>(s_w + (3 * mm + 1) * 128);
        ulonglong2 w2 = *reinterpret_cast<const ulonglong2*>(s_w + (3 * mm + 2) * 128);
#pragma unroll
        for (int j = 0; j < 20; j++) {
            ulonglong2 v = *reinterpret_cast<const ulonglong2*>(s_x + j * STRIDE + 4 * mm);
            if (j < 18)            { fma2(acc[j], v.x, w0.x);     fma2(acc[j], v.y, w0.y); }
            if (j >= 1 && j <= 18) { fma2(acc[j - 1], v.x, w1.x); fma2(acc[j - 1], v.y, w1.y); }
            if (j >= 2)            { fma2(acc[j - 2], v.x, w2.x); fma2(acc[j - 2], v.y, w2.y); }
        }
    }
#pragma unroll
    for (int j = 0; j < 18; j++)
        h1T[j * 32] = fmaxf(hsum2(acc[j]) + bv, 0.f);
}

DEVINL float conv2Q(const float* __restrict__ h1T, const float* __restrict__ s_w,
                    float bv) {
    ull acc[16];
#pragma unroll
    for (int j = 0; j < 16; j++) acc[j] = 0ull;
#pragma unroll 2
    for (int mm = 0; mm < 8; mm++) {
        ulonglong2 w0 = *reinterpret_cast<const ulonglong2*>(s_w + (3 * mm + 0) * 128);
        ulonglong2 w1 = *reinterpret_cast<const ulonglong2*>(s_w + (3 * mm + 1) * 128);
        ulonglong2 w2 = *reinterpret_cast<const ulonglong2*>(s_w + (3 * mm + 2) * 128);
#pragma unroll
        for (int j = 0; j < 18; j++) {
            ulonglong2 v = *reinterpret_cast<const ulonglong2*>(h1T + j * 32 + 4 * mm);
            if (j < 16)            { fma2(acc[j], v.x, w0.x);     fma2(acc[j], v.y, w0.y); }
            if (j >= 1 && j <= 16) { fma2(acc[j - 1], v.x, w1.x); fma2(acc[j - 1], v.y, w1.y); }
            if (j >= 2)            { fma2(acc[j - 2], v.x, w2.x); fma2(acc[j - 2], v.y, w2.y); }
        }
    }
    float s = 0.f;
#pragma unroll
    for (int j = 0; j < 16; j++)
        s += fmaxf(hsum2(acc[j]) + bv, 0.f);
    return s * (1.f / 16.f);
}

// one-row matvec for gate `tid`: xg + Whh[tid].h  (8 chains, 3-level reduce)
DEVINL float lstm_matvec(const ull* __restrict__ wreg, const float* __restrict__ s_h,
                         float xcur) {
    ull a[8];
    a[0] = pack2(xcur, 0.f);
#pragma unroll
    for (int i = 1; i < 8; i++) a[i] = 0ull;
    const ulonglong2* h2 = reinterpret_cast<const ulonglong2*>(s_h);
#pragma unroll
    for (int q = 0; q < 16; q++) {
        ulonglong2 hv = h2[q];
        fma2(a[(2 * q) & 7], wreg[2 * q], hv.x);
        fma2(a[(2 * q + 1) & 7], wreg[2 * q + 1], hv.y);
    }
    add2(a[0], a[0], a[4]);
    add2(a[1], a[1], a[5]);
    add2(a[2], a[2], a[6]);
    add2(a[3], a[3], a[7]);
    add2(a[0], a[0], a[2]);
    add2(a[1], a[1], a[3]);
    add2(a[0], a[0], a[1]);
    return hsum2(a[0]);
}

// ---------------------------------------------------------------------------
// Fused kernel. Blocks 0..31: LSTM+head role (2 batch rows each).
// Blocks 32..1055: enc role producing (b = k&63, tc = k>>6).
// ---------------------------------------------------------------------------
__global__ void __launch_bounds__(256) fused_kernel(
    const float* __restrict__ pressure, const float* __restrict__ torque,
    const float* __restrict__ frag,
    const float* __restrict__ pw1, const float* __restrict__ pb1,
    const float* __restrict__ pw2, const float* __restrict__ pb2,
    const float* __restrict__ tw1, const float* __restrict__ tb1,
    const float* __restrict__ tw2, const float* __restrict__ tb2,
    const float* __restrict__ fw, const float* __restrict__ fb,
    const float* __restrict__ prw, const float* __restrict__ prb,
    const float* __restrict__ Wih, const float* __restrict__ bih,
    const float* __restrict__ bhh, const float* __restrict__ Whh,
    const float* __restrict__ hw, const float* __restrict__ hb,
    float* __restrict__ out) {
    extern __shared__ float sm[];
    const int tid = threadIdx.x;

    if (blockIdx.x < NLSTM) {
        // =================== LSTM + head role (2 rows) ===================
        __shared__ __align__(16) float s_h0[PROJ], s_h1[PROJ];
        __shared__ float s_g0[NG], s_g1[NG];
        __shared__ __align__(16) float s_hw[4 * PROJ];
        __shared__ float s_hb[4];
        __shared__ __align__(16) float s_hbuf[2][16 * PROJ];

        const int b0 = blockIdx.x * 2, b1 = b0 + 1;
        const int cls = tid >> 6;  // gate class of gate `tid`

        ull wreg[PROJ / 2];        // Whh row `tid`, shared across both rows
        {
            const ulonglong2* w2 = reinterpret_cast<const ulonglong2*>(Whh + tid * PROJ);
#pragma unroll
            for (int q = 0; q < PROJ / 4; q++) {
                ulonglong2 v = w2[q];
                wreg[2 * q] = v.x;
                wreg[2 * q + 1] = v.y;
            }
        }

        s_hw[tid] = hw[tid];
        if (tid < 4) s_hb[tid] = hb[tid];
        if (tid < PROJ) { s_h0[tid] = 0.f; s_h1[tid] = 0.f; }
        float c = 0.f;   // row0's c in threads 0..63; row1's in 64..127

        const float* xg0 = g_xg + b0 * T * NG;
        const float* xg1 = g_xg + b1 * T * NG;
        __syncthreads();

        for (int ch = 0; ch < NCHUNK; ch++) {
            // wait for producers of chunk ch for both rows; self-reset
            if (tid < 2) {
                int* fp = &g_flag[(tid ? b1 : b0) * NCHUNK + ch];
                while (atomicAdd(fp, 0) == 0) { }
                atomicExch(fp, 0);
            }
            __syncthreads();

            float xn0 = xg0[(ch * 16) * NG + tid];
            float xn1 = xg1[(ch * 16) * NG + tid];
#pragma unroll 1
            for (int tt = 0; tt < 16; tt++) {
                float xc0 = xn0, xc1 = xn1;
                if (tt < 15) {
                    xn0 = xg0[(ch * 16 + tt + 1) * NG + tid];
                    xn1 = xg1[(ch * 16 + tt + 1) * NG + tid];
                }

                float gv0 = lstm_matvec(wreg, s_h0, xc0);
                float gv1 = lstm_matvec(wreg, s_h1, xc1);
                s_g0[tid] = (cls == 2) ? tanh_(gv0) : sigm(gv0);
                s_g1[tid] = (cls == 2) ? tanh_(gv1) : sigm(gv1);
                __syncthreads();

                if (tid < PROJ) {
                    float ai = s_g0[tid];
                    float af = s_g0[PROJ + tid];
                    float ag = s_g0[2 * PROJ + tid];
                    float ao = s_g0[3 * PROJ + tid];
                    c = fmaf(af, c, ai * ag);
                    float h = ao * tanh_(c);
                    s_h0[tid] = h;
                    s_hbuf[0][tt * PROJ + tid] = h;
                } else if (tid < 2 * PROJ) {
                    int j = tid - PROJ;
                    float ai = s_g1[j];
                    float af = s_g1[PROJ + j];
                    float ag = s_g1[2 * PROJ + j];
                    float ao = s_g1[3 * PROJ + j];
                    c = fmaf(af, c, ai * ag);
                    float h = ao * tanh_(c);
                    s_h1[j] = h;
                    s_hbuf[1][tt * PROJ + j] = h;
                }
                __syncthreads();
            }

            // ---- head for this chunk: 2 rows x 16 tt x 4 m, 2 threads each ----
            {
                int r = tid >> 7;                 // row 0/1
                int u = tid & 127;
                int tt = u >> 3, m = (u >> 1) & 3, part = u & 1;
                const float* hv = s_hbuf[r] + tt * PROJ + part * 32;
                const float* wv = s_hw + m * PROJ + part * 32;
                float acc = (part == 0) ? s_hb[m] : 0.f;
#pragma unroll
                for (int j = 0; j < 32; j++) acc = fmaf(wv[j], hv[j], acc);
                acc += __shfl_xor_sync(0xffffffffu, acc, 1);
                if (part == 0) {
                    int b = r ? b1 : b0;
                    out[(b * T + ch * 16 + tt) * 4 + m] = sigm(acc);
                }
            }
            // s_hbuf reuse next chunk ordered by the spin + syncthreads above
        }

        if (tid < PROJ) {
            out[B * T * 4 + b0 * PROJ + tid] = s_h0[tid];            // hT row0
            out[B * T * 4 + B * PROJ + b0 * PROJ + tid] = c;         // cT row0
        } else if (tid < 2 * PROJ) {
            int j = tid - PROJ;
            out[B * T * 4 + b1 * PROJ + j] = s_h1[j];                // hT row1
            out[B * T * 4 + B * PROJ + b1 * PROJ + j] = c;           // cT row1
        }
        return;
    }

    // ======================= Encoder role (r12, unchanged) =======================
    const int k = blockIdx.x - NLSTM;
    const int b = k & 63;
    const int tc = k >> 6;
    const int lane = tid & 31;
    const int warp = tid >> 5;

    // ---- stage weights ----
    for (int t = tid; t < 32 * 3 * 3; t += 256) {         // conv1p pairs
        int o = t / 9, rem = t % 9, m = rem / 3, kk = rem % 3;
        int di = OFF_W1P + (3 * m + kk) * 64 + 2 * o;
        sm[di]     = pw1[(o * NP + 2 * m) * 3 + kk];
        sm[di + 1] = pw1[(o * NP + 2 * m + 1) * 3 + kk];
    }
    for (int t = tid; t < 32 * 3 * 3; t += 256) {         // conv1t quads
        int o = t / 9, rem = t % 9, mm = rem / 3, kk = rem % 3;
        int di = OFF_W1T + (3 * mm + kk) * 128 + 4 * o;
#pragma unroll
        for (int q = 0; q < 4; q++)
            sm[di + q] = tw1[(o * NT + 4 * mm + q) * 3 + kk];
    }
    for (int t = tid; t < 32 * 8 * 3; t += 256) {         // conv2 quads
        int o = t / 24, rem = t % 24, mm = rem / 3, kk = rem % 3;
        int di = (3 * mm + kk) * 128 + 4 * o;
#pragma unroll
        for (int q = 0; q < 4; q++) {
            int si = (o * CC + 4 * mm + q) * 3 + kk;
            sm[OFF_W2P + di + q] = pw2[si];
            sm[OFF_W2T + di + q] = tw2[si];
        }
    }
    for (int t = tid; t < 36 * 32; t += 256) {            // prwT quad-pack
        int q = t >> 5, o = t & 31;
        int di = OFF_PRW + q * 128 + o * 4;
        sm[di + 0] = prw[o * 72 + 2 * q];
        sm[di + 1] = prw[(o + 32) * 72 + 2 * q];
        sm[di + 2] = prw[o * 72 + 2 * q + 1];
        sm[di + 3] = prw[(o + 32) * 72 + 2 * q + 1];
    }
    if (tid < 32) {
        sm[OFF_B1P + tid] = pb1[tid]; sm[OFF_B1T + tid] = tb1[tid];
        sm[OFF_B2P + tid] = pb2[tid]; sm[OFF_B2T + tid] = tb2[tid];
    }
    sm[OFF_BIAS + tid] = bih[tid] + bhh[tid];
    __syncthreads();

    const int wbase = b * 256 + tc * 16;   // wi = wbase + win, win = 0..15

    float* sxp = sm + OFF_XP + warp * 128;
    float* sxt = sm + OFF_XT + warp * 256;
    float* sh1 = sm + OFF_H1 + warp * 576;
    float* sft = sm + OFF_CAT + warp * 80;

#pragma unroll 1
    for (int w2 = 0; w2 < 2; w2++) {
        const int win = warp * 2 + w2;
        const int wi = wbase + win;
        float* spj = sm + OFF_PRJ + win * 64;

        // ---- load window inputs (raw [pos][ch] layout kept) ----
        {
            const float4* gp4 = reinterpret_cast<const float4*>(pressure + wi * 120);
            if (lane < 30) reinterpret_cast<float4*>(sxp)[lane] = gp4[lane];
            const float4* gt4 = reinterpret_cast<const float4*>(torque + wi * 240);
            reinterpret_cast<float4*>(sxt)[lane] = gt4[lane];
            if (lane < 28) reinterpret_cast<float4*>(sxt)[lane + 32] = gt4[lane + 32];
        }
        __syncwarp();

        // ---- pressure: conv1 -> h1T -> conv2 -> pooled ----
        conv1P<3, NP>(sxp, sm + OFF_W1P + 2 * lane, sm[OFF_B1P + lane], sh1 + lane);
        __syncwarp();
        float poolp = conv2Q(sh1, sm + OFF_W2P + 4 * lane, sm[OFF_B2P + lane]);
        __syncwarp();

        // ---- torque: conv1 -> h1T -> conv2 -> pooled ----
        conv1Q<3, NT>(sxt, sm + OFF_W1T + 4 * lane, sm[OFF_B1T + lane], sh1 + lane);
        __syncwarp();
        float poolt = conv2Q(sh1, sm + OFF_W2T + 4 * lane, sm[OFF_B2T + lane]);

        sft[lane] = poolp;
        sft[32 + lane] = poolt;
        if (lane < FD) sft[64 + lane] = fmaxf(fmaf(frag[b], fw[lane], fb[lane]), 0.f);
        __syncwarp();

        // ---- projection: packed (o, o+32) outputs from smem prwT ----
        {
            ull acc = 0ull, accb = 0ull;
            const float* sw = sm + OFF_PRW + 4 * lane;
#pragma unroll
            for (int q = 0; q < 36; q++) {
                ulonglong2 wq = *reinterpret_cast<const ulonglong2*>(sw + q * 128);
                ull xp = *reinterpret_cast<const ull*>(sft + 2 * q);
                float x0, x1; upk(xp, x0, x1);
                fma2(acc,  wq.x, pack2(x0, x0));
                fma2(accb, wq.y, pack2(x1, x1));
            }
            add2(acc, acc, accb);
            float lo, hi; upk(acc, lo, hi);
            spj[lane]      = fmaxf(lo + prb[lane], 0.f);
            spj[lane + 32] = fmaxf(hi + prb[lane + 32], 0.f);
        }
        __syncwarp();
    }
    __syncthreads();

    // ---- xg: gate tid for all 16 windows; Wih row held in registers ----
    {
        ull wv[32];
        const ulonglong2* wr = reinterpret_cast<const ulonglong2*>(Wih + tid * PROJ);
#pragma unroll
        for (int q = 0; q < 16; q++) {
            ulonglong2 v = wr[q];
            wv[2 * q] = v.x; wv[2 * q + 1] = v.y;
        }
        float bias = sm[OFF_BIAS + tid];
#pragma unroll 2
        for (int win = 0; win < WPB; win++) {
            const ulonglong2* fr = reinterpret_cast<const ulonglong2*>(sm + OFF_PRJ + win * 64);
            ull a0 = pack2(bias, 0.f), a1 = 0ull, a2 = 0ull, a3 = 0ull;
#pragma unroll
            for (int q = 0; q < 16; q++) {
                ulonglong2 fv = fr[q];
                if ((q & 1) == 0) { fma2(a0, wv[2 * q], fv.x); fma2(a1, wv[2 * q + 1], fv.y); }
                else              { fma2(a2, wv[2 * q], fv.x); fma2(a3, wv[2 * q + 1], fv.y); }
            }
            add2(a0, a0, a2);
            add2(a1, a1, a3);
            add2(a0, a0, a1);
            g_xg[(wbase + win) * NG + tid] = hsum2(a0);
        }
    }

    // ---- publish chunk ----
    __syncthreads();
    if (tid == 0) {
        __threadfence();
        atomicExch(&g_flag[b * NCHUNK + tc], 1);
    }
}

// ---------------------------------------------------------------------------
extern "C" void kernel_launch(void* const* d_in, const int* in_sizes, int n_in,
                              void* d_out, int out_size) {
    const float* pressure = (const float*)d_in[0];
    const float* torque   = (const float*)d_in[1];
    const float* frag     = (const float*)d_in[2];
    const float* pw1 = (const float*)d_in[3];
    const float* pb1 = (const float*)d_in[4];
    const float* pw2 = (const float*)d_in[5];
    const float* pb2 = (const float*)d_in[6];
    const float* tw1 = (const float*)d_in[7];
    const float* tb1 = (const float*)d_in[8];
    const float* tw2 = (const float*)d_in[9];
    const float* tb2 = (const float*)d_in[10];
    const float* fw  = (const float*)d_in[11];
    const float* fb  = (const float*)d_in[12];
    const float* prw = (const float*)d_in[13];
    const float* prb = (const float*)d_in[14];
    const float* Wih = (const float*)d_in[15];
    const float* Whh = (const float*)d_in[16];
    const float* bih = (const float*)d_in[17];
    const float* bhh = (const float*)d_in[18];
    const float* hw  = (const float*)d_in[19];
    const float* hb  = (const float*)d_in[20];

    static bool attr_set = false;
    if (!attr_set) {
        cudaFuncSetAttribute(fused_kernel, cudaFuncAttributeMaxDynamicSharedMemorySize,
                             SMEM_BYTES);
        attr_set = true;
    }

    fused_kernel<<<NLSTM + NWIN / WPB, 256, SMEM_BYTES>>>(
        pressure, torque, frag,
        pw1, pb1, pw2, pb2, tw1, tb1, tw2, tb2,
        fw, fb, prw, prb, Wih, bih, bhh, Whh, hw, hb, (float*)d_out);
}

// round 15
// speedup vs baseline: 1.0472x; 1.0472x over previous
#include <cuda_runtime.h>

#define DEVINL __device__ __forceinline__
typedef unsigned long long ull;

constexpr int B = 64, T = 256, W = 20, NP = 6, NT = 12, CC = 32, FD = 8, PROJ = 64;
constexpr int NG = 4 * PROJ;            // 256 gates
constexpr int NWIN = B * T;             // 16384
constexpr int WPB = 16;                 // windows per enc block (2 per warp)
constexpr int NCHUNK = 16;              // t-chunks per batch row

// scratch
__device__ float g_xg[NWIN * NG];       // 16 MB
__device__ int   g_flag[B * NCHUNK];    // chunk flags (self-resetting, start 0)

DEVINL void fma2(ull& d, ull a, ull b) {
    asm("fma.rn.f32x2 %0, %1, %2, %0;" : "+l"(d) : "l"(a), "l"(b));
}
DEVINL void add2(ull& d, ull a, ull b) {
    asm("add.rn.f32x2 %0, %1, %2;" : "=l"(d) : "l"(a), "l"(b));
}
DEVINL float hsum2(ull a) {
    float lo, hi;
    asm("mov.b64 {%0,%1}, %2;" : "=f"(lo), "=f"(hi) : "l"(a));
    return lo + hi;
}
DEVINL ull pack2(float lo, float hi) {
    ull r;
    asm("mov.b64 %0, {%1,%2};" : "=l"(r) : "f"(lo), "f"(hi));
    return r;
}
DEVINL void upk(ull a, float& lo, float& hi) {
    asm("mov.b64 {%0,%1}, %2;" : "=f"(lo), "=f"(hi) : "l"(a));
}

DEVINL float sigm(float x) { return __fdividef(1.f, 1.f + __expf(-x)); }
DEVINL float tanh_(float x) { return __fdividef(2.f, 1.f + __expf(-2.f * x)) - 1.f; }

// ---------------------------------------------------------------------------
// dynamic smem layout (floats), enc role
// ---------------------------------------------------------------------------
constexpr int OFF_W1P  = 0;                       // 576
constexpr int OFF_W1T  = OFF_W1P + 576;           // 1152
constexpr int OFF_W2P  = OFF_W1T + 1152;          // 3072
constexpr int OFF_W2T  = OFF_W2P + 3072;          // 3072
constexpr int OFF_B1P  = OFF_W2T + 3072;          // 32
constexpr int OFF_B1T  = OFF_B1P + 32;            // 32
constexpr int OFF_B2P  = OFF_B1T + 32;            // 32
constexpr int OFF_B2T  = OFF_B2P + 32;            // 32
constexpr int OFF_BIAS = OFF_B2T + 32;            // 256
constexpr int OFF_XP   = OFF_BIAS + 256;          // 8 * 128
constexpr int OFF_XT   = OFF_XP + 8 * 128;        // 8 * 256
constexpr int OFF_H1   = OFF_XT + 8 * 256;        // 8 * 1152 (two windows/warp)
constexpr int OFF_PRJ  = OFF_H1 + 8 * 1152;       // 16 * 64
constexpr int OFF_PRW  = OFF_PRJ + 16 * 64;       // 4608
constexpr int SMEM_FLOATS = OFF_PRW + 4608;       // 26176
constexpr int SMEM_BYTES = SMEM_FLOATS * 4;       // 104704 B -> 2 blocks/SM

// lstm role overlay of the same dynamic region:
constexpr int LOFF_H    = 0;      // 64
constexpr int LOFF_GACT = 64;     // 256
constexpr int LOFF_HW   = 320;    // 256
constexpr int LOFF_HB   = 576;    // 4
constexpr int LOFF_HBUF = 640;    // 16 * 64

// ---------------------------------------------------------------------------
// conv1 helpers (single window, unchanged)
// ---------------------------------------------------------------------------
template <int NPAIR, int STRIDE>
DEVINL void conv1P(const float* __restrict__ s_x, const float* __restrict__ s_w,
                   float bv, float* __restrict__ h1T) {
    ull acc[18];
#pragma unroll
    for (int j = 0; j < 18; j++) acc[j] = 0ull;
#pragma unroll
    for (int m = 0; m < NPAIR; m++) {
        ull w0 = *reinterpret_cast<const ull*>(s_w + (3 * m + 0) * 64);
        ull w1 = *reinterpret_cast<const ull*>(s_w + (3 * m + 1) * 64);
        ull w2 = *reinterpret_cast<const ull*>(s_w + (3 * m + 2) * 64);
#pragma unroll
        for (int j = 0; j < 20; j++) {
            ull v = *reinterpret_cast<const ull*>(s_x + j * STRIDE + 2 * m);
            if (j < 18) fma2(acc[j], v, w0);
            if (j >= 1 && j <= 18) fma2(acc[j - 1], v, w1);
            if (j >= 2) fma2(acc[j - 2], v, w2);
        }
    }
#pragma unroll
    for (int j = 0; j < 18; j++)
        h1T[j * 32] = fmaxf(hsum2(acc[j]) + bv, 0.f);
}

template <int NQUAD, int STRIDE>
DEVINL void conv1Q(const float* __restrict__ s_x, const float* __restrict__ s_w,
                   float bv, float* __restrict__ h1T) {
    ull acc[18];
#pragma unroll
    for (int j = 0; j < 18; j++) acc[j] = 0ull;
#pragma unroll
    for (int mm = 0; mm < NQUAD; mm++) {
        ulonglong2 w0 = *reinterpret_cast<const ulonglong2*>(s_w + (3 * mm + 0) * 128);
        ulonglong2 w1 = *reinterpret_cast<const ulonglong2*>(s_w + (3 * mm + 1) * 128);
        ulonglong2 w2 = *reinterpret_cast<const ulonglong2*>(s_w + (3 * mm + 2) * 128);
#pragma unroll
        for (int j = 0; j < 20; j++) {
            ulonglong2 v = *reinterpret_cast<const ulonglong2*>(s_x + j * STRIDE + 4 * mm);
            if (j < 18)            { fma2(acc[j], v.x, w0.x);     fma2(acc[j], v.y, w0.y); }
            if (j >= 1 && j <= 18) { fma2(acc[j - 1], v.x, w1.x); fma2(acc[j - 1], v.y, w1.y); }
            if (j >= 2)            { fma2(acc[j - 2], v.x, w2.x); fma2(acc[j - 2], v.y, w2.y); }
        }
    }
#pragma unroll
    for (int j = 0; j < 18; j++)
        h1T[j * 32] = fmaxf(hsum2(acc[j]) + bv, 0.f);
}

// ---------------------------------------------------------------------------
// DUAL-window conv2: one weight fetch feeds both windows' accumulators.
// ---------------------------------------------------------------------------
DEVINL void conv2Q_dual(const float* __restrict__ h1A, const float* __restrict__ h1B,
                        const float* __restrict__ s_w, float bv,
                        float& pA, float& pB) {
    ull aA[16], aB[16];
#pragma unroll
    for (int j = 0; j < 16; j++) { aA[j] = 0ull; aB[j] = 0ull; }
#pragma unroll 2
    for (int mm = 0; mm < 8; mm++) {
        ulonglong2 w0 = *reinterpret_cast<const ulonglong2*>(s_w + (3 * mm + 0) * 128);
        ulonglong2 w1 = *reinterpret_cast<const ulonglong2*>(s_w + (3 * mm + 1) * 128);
        ulonglong2 w2 = *reinterpret_cast<const ulonglong2*>(s_w + (3 * mm + 2) * 128);
#pragma unroll
        for (int j = 0; j < 18; j++) {
            ulonglong2 vA = *reinterpret_cast<const ulonglong2*>(h1A + j * 32 + 4 * mm);
            ulonglong2 vB = *reinterpret_cast<const ulonglong2*>(h1B + j * 32 + 4 * mm);
            if (j < 16) {
                fma2(aA[j], vA.x, w0.x); fma2(aA[j], vA.y, w0.y);
                fma2(aB[j], vB.x, w0.x); fma2(aB[j], vB.y, w0.y);
            }
            if (j >= 1 && j <= 16) {
                fma2(aA[j - 1], vA.x, w1.x); fma2(aA[j - 1], vA.y, w1.y);
                fma2(aB[j - 1], vB.x, w1.x); fma2(aB[j - 1], vB.y, w1.y);
            }
            if (j >= 2) {
                fma2(aA[j - 2], vA.x, w2.x); fma2(aA[j - 2], vA.y, w2.y);
                fma2(aB[j - 2], vB.x, w2.x); fma2(aB[j - 2], vB.y, w2.y);
            }
        }
    }
    float sA = 0.f, sB = 0.f;
#pragma unroll
    for (int j = 0; j < 16; j++) {
        sA += fmaxf(hsum2(aA[j]) + bv, 0.f);
        sB += fmaxf(hsum2(aB[j]) + bv, 0.f);
    }
    pA = sA * (1.f / 16.f);
    pB = sB * (1.f / 16.f);
}

// ---------------------------------------------------------------------------
// Fused kernel. Blocks 0..63: LSTM+head role. Blocks 64..1087: enc role.
// ---------------------------------------------------------------------------
__global__ void __launch_bounds__(256) fused_kernel(
    const float* __restrict__ pressure, const float* __restrict__ torque,
    const float* __restrict__ frag,
    const float* __restrict__ pw1, const float* __restrict__ pb1,
    const float* __restrict__ pw2, const float* __restrict__ pb2,
    const float* __restrict__ tw1, const float* __restrict__ tb1,
    const float* __restrict__ tw2, const float* __restrict__ tb2,
    const float* __restrict__ fw, const float* __restrict__ fb,
    const float* __restrict__ prw, const float* __restrict__ prb,
    const float* __restrict__ Wih, const float* __restrict__ bih,
    const float* __restrict__ bhh, const float* __restrict__ Whh,
    const float* __restrict__ hw, const float* __restrict__ hb,
    float* __restrict__ out) {
    extern __shared__ float sm[];
    const int tid = threadIdx.x;

    if (blockIdx.x < 64) {
        // =================== LSTM + head role (r12, dyn-smem) ===================
        float* s_h    = sm + LOFF_H;
        float* s_gact = sm + LOFF_GACT;
        float* s_hw   = sm + LOFF_HW;
        float* s_hb   = sm + LOFF_HB;
        float* s_hbuf = sm + LOFF_HBUF;

        const int b = blockIdx.x;
        const int cls = tid >> 6;  // 0:i 1:f 2:g 3:o

        ull wreg[PROJ / 2];
        {
            const ulonglong2* w2 = reinterpret_cast<const ulonglong2*>(Whh + tid * PROJ);
#pragma unroll
            for (int q = 0; q < PROJ / 4; q++) {
                ulonglong2 v = w2[q];
                wreg[2 * q] = v.x;
                wreg[2 * q + 1] = v.y;
            }
        }

        s_hw[tid] = hw[tid];
        if (tid < 4) s_hb[tid] = hb[tid];
        if (tid < PROJ) s_h[tid] = 0.f;
        float c = 0.f;

        const float* xg = g_xg + b * T * NG;
        __syncthreads();

        for (int ch = 0; ch < NCHUNK; ch++) {
            if (tid == 0) {
                int* fp = &g_flag[b * NCHUNK + ch];
                while (atomicAdd(fp, 0) == 0) { }
                atomicExch(fp, 0);
            }
            __syncthreads();

            float xnext = xg[(ch * 16) * NG + tid];
#pragma unroll 1
            for (int tt = 0; tt < 16; tt++) {
                float xcur = xnext;
                if (tt < 15) xnext = xg[(ch * 16 + tt + 1) * NG + tid];

                ull a[8];
                a[0] = pack2(xcur, 0.f);
#pragma unroll
                for (int i = 1; i < 8; i++) a[i] = 0ull;
                const ulonglong2* h2 = reinterpret_cast<const ulonglong2*>(s_h);
#pragma unroll
                for (int q = 0; q < 16; q++) {
                    ulonglong2 hv = h2[q];
                    fma2(a[(2 * q) & 7], wreg[2 * q], hv.x);
                    fma2(a[(2 * q + 1) & 7], wreg[2 * q + 1], hv.y);
                }
                add2(a[0], a[0], a[4]);
                add2(a[1], a[1], a[5]);
                add2(a[2], a[2], a[6]);
                add2(a[3], a[3], a[7]);
                add2(a[0], a[0], a[2]);
                add2(a[1], a[1], a[3]);
                add2(a[0], a[0], a[1]);
                float g = hsum2(a[0]);
                s_gact[tid] = (cls == 2) ? tanh_(g) : sigm(g);
                __syncthreads();

                if (tid < PROJ) {
                    float ai = s_gact[tid];
                    float af = s_gact[PROJ + tid];
                    float ag = s_gact[2 * PROJ + tid];
                    float ao = s_gact[3 * PROJ + tid];
                    c = fmaf(af, c, ai * ag);
                    float h = ao * tanh_(c);
                    s_h[tid] = h;
                    s_hbuf[tt * PROJ + tid] = h;
                }
                __syncthreads();
            }

            // ---- head for this chunk: 64 outputs, 4 threads each ----
            {
                int tt = tid >> 4, m = (tid >> 2) & 3, part = tid & 3;
                const float* hv = s_hbuf + tt * PROJ + part * 16;
                const float* wv = s_hw + m * PROJ + part * 16;
                float acc = (part == 0) ? s_hb[m] : 0.f;
#pragma unroll
                for (int j = 0; j < 16; j++) acc = fmaf(wv[j], hv[j], acc);
                acc += __shfl_xor_sync(0xffffffffu, acc, 1);
                acc += __shfl_xor_sync(0xffffffffu, acc, 2);
                if (part == 0)
                    out[(b * T + ch * 16 + tt) * 4 + m] = sigm(acc);
            }
        }

        if (tid < PROJ) {
            out[B * T * 4 + b * PROJ + tid] = s_h[tid];             // hT
            out[B * T * 4 + B * PROJ + b * PROJ + tid] = c;         // cT
        }
        return;
    }

    // ======================= Encoder role (dual-window conv2/proj) =======================
    const int k = blockIdx.x - 64;
    const int b = k & 63;
    const int tc = k >> 6;
    const int lane = tid & 31;
    const int warp = tid >> 5;

    // ---- stage weights ----
    for (int t = tid; t < 32 * 3 * 3; t += 256) {         // conv1p pairs
        int o = t / 9, rem = t % 9, m = rem / 3, kk = rem % 3;
        int di = OFF_W1P + (3 * m + kk) * 64 + 2 * o;
        sm[di]     = pw1[(o * NP + 2 * m) * 3 + kk];
        sm[di + 1] = pw1[(o * NP + 2 * m + 1) * 3 + kk];
    }
    for (int t = tid; t < 32 * 3 * 3; t += 256) {         // conv1t quads
        int o = t / 9, rem = t % 9, mm = rem / 3, kk = rem % 3;
        int di = OFF_W1T + (3 * mm + kk) * 128 + 4 * o;
#pragma unroll
        for (int q = 0; q < 4; q++)
            sm[di + q] = tw1[(o * NT + 4 * mm + q) * 3 + kk];
    }
    for (int t = tid; t < 32 * 8 * 3; t += 256) {         // conv2 quads
        int o = t / 24, rem = t % 24, mm = rem / 3, kk = rem % 3;
        int di = (3 * mm + kk) * 128 + 4 * o;
#pragma unroll
        for (int q = 0; q < 4; q++) {
            int si = (o * CC + 4 * mm + q) * 3 + kk;
            sm[OFF_W2P + di + q] = pw2[si];
            sm[OFF_W2T + di + q] = tw2[si];
        }
    }
    for (int t = tid; t < 36 * 32; t += 256) {            // prwT quad-pack
        int q = t >> 5, o = t & 31;
        int di = OFF_PRW + q * 128 + o * 4;
        sm[di + 0] = prw[o * 72 + 2 * q];
        sm[di + 1] = prw[(o + 32) * 72 + 2 * q];
        sm[di + 2] = prw[o * 72 + 2 * q + 1];
        sm[di + 3] = prw[(o + 32) * 72 + 2 * q + 1];
    }
    if (tid < 32) {
        sm[OFF_B1P + tid] = pb1[tid]; sm[OFF_B1T + tid] = tb1[tid];
        sm[OFF_B2P + tid] = pb2[tid]; sm[OFF_B2T + tid] = tb2[tid];
    }
    sm[OFF_BIAS + tid] = bih[tid] + bhh[tid];
    __syncthreads();

    const int wbase = b * 256 + tc * 16;   // wi = wbase + win, win = 0..15
    const int wiA = wbase + warp * 2;
    const int wiB = wiA + 1;

    float* sxp  = sm + OFF_XP + warp * 128;
    float* sxt  = sm + OFF_XT + warp * 256;
    float* sh1A = sm + OFF_H1 + warp * 1152;
    float* sh1B = sh1A + 576;
    float* spjA = sm + OFF_PRJ + (warp * 2) * 64;
    float* spjB = spjA + 64;

    // ---- pressure A ----
    {
        const float4* gp4 = reinterpret_cast<const float4*>(pressure + wiA * 120);
        if (lane < 30) reinterpret_cast<float4*>(sxp)[lane] = gp4[lane];
    }
    __syncwarp();
    conv1P<3, NP>(sxp, sm + OFF_W1P + 2 * lane, sm[OFF_B1P + lane], sh1A + lane);
    __syncwarp();
    // ---- pressure B ----
    {
        const float4* gp4 = reinterpret_cast<const float4*>(pressure + wiB * 120);
        if (lane < 30) reinterpret_cast<float4*>(sxp)[lane] = gp4[lane];
    }
    __syncwarp();
    conv1P<3, NP>(sxp, sm + OFF_W1P + 2 * lane, sm[OFF_B1P + lane], sh1B + lane);
    __syncwarp();
    // ---- dual conv2-p ----
    float poolpA, poolpB;
    conv2Q_dual(sh1A, sh1B, sm + OFF_W2P + 4 * lane, sm[OFF_B2P + lane], poolpA, poolpB);
    __syncwarp();

    // ---- torque A ----
    {
        const float4* gt4 = reinterpret_cast<const float4*>(torque + wiA * 240);
        reinterpret_cast<float4*>(sxt)[lane] = gt4[lane];
        if (lane < 28) reinterpret_cast<float4*>(sxt)[lane + 32] = gt4[lane + 32];
    }
    __syncwarp();
    conv1Q<3, NT>(sxt, sm + OFF_W1T + 4 * lane, sm[OFF_B1T + lane], sh1A + lane);
    __syncwarp();
    // ---- torque B ----
    {
        const float4* gt4 = reinterpret_cast<const float4*>(torque + wiB * 240);
        reinterpret_cast<float4*>(sxt)[lane] = gt4[lane];
        if (lane < 28) reinterpret_cast<float4*>(sxt)[lane + 32] = gt4[lane + 32];
    }
    __syncwarp();
    conv1Q<3, NT>(sxt, sm + OFF_W1T + 4 * lane, sm[OFF_B1T + lane], sh1B + lane);
    __syncwarp();
    // ---- dual conv2-t ----
    float pooltA, pooltB;
    conv2Q_dual(sh1A, sh1B, sm + OFF_W2T + 4 * lane, sm[OFF_B2T + lane], pooltA, pooltB);
    __syncwarp();

    // ---- cat (overlays dead h1): sftA at sh1A, sftB at sh1A+128 ----
    float* sftA = sh1A;
    float* sftB = sh1A + 128;
    sftA[lane] = poolpA;
    sftA[32 + lane] = pooltA;
    sftB[lane] = poolpB;
    sftB[32 + lane] = pooltB;
    if (lane < FD) {
        float fv = fmaxf(fmaf(frag[b], fw[lane], fb[lane]), 0.f);
        sftA[64 + lane] = fv;
        sftB[64 + lane] = fv;
    }
    __syncwarp();

    // ---- dual projection: one prwT fetch feeds both windows ----
    {
        ull aA = 0ull, bA = 0ull, aB = 0ull, bB = 0ull;
        const float* sw = sm + OFF_PRW + 4 * lane;
#pragma unroll
        for (int q = 0; q < 36; q++) {
            ulonglong2 wq = *reinterpret_cast<const ulonglong2*>(sw + q * 128);
            ull xpa = *reinterpret_cast<const ull*>(sftA + 2 * q);
            ull xpb = *reinterpret_cast<const ull*>(sftB + 2 * q);
            float a0, a1, b0, b1;
            upk(xpa, a0, a1);
            upk(xpb, b0, b1);
            fma2(aA, wq.x, pack2(a0, a0));
            fma2(bA, wq.y, pack2(a1, a1));
            fma2(aB, wq.x, pack2(b0, b0));
            fma2(bB, wq.y, pack2(b1, b1));
        }
        add2(aA, aA, bA);
        add2(aB, aB, bB);
        float loA, hiA, loB, hiB;
        upk(aA, loA, hiA);
        upk(aB, loB, hiB);
        float pb0 = prb[lane], pb32 = prb[lane + 32];
        spjA[lane]      = fmaxf(loA + pb0, 0.f);
        spjA[lane + 32] = fmaxf(hiA + pb32, 0.f);
        spjB[lane]      = fmaxf(loB + pb0, 0.f);
        spjB[lane + 32] = fmaxf(hiB + pb32, 0.f);
    }
    __syncthreads();

    // ---- xg: gate tid for all 16 windows; Wih row held in registers ----
    {
        ull wv[32];
        const ulonglong2* wr = reinterpret_cast<const ulonglong2*>(Wih + tid * PROJ);
#pragma unroll
        for (int q = 0; q < 16; q++) {
            ulonglong2 v = wr[q];
            wv[2 * q] = v.x; wv[2 * q + 1] = v.y;
        }
        float bias = sm[OFF_BIAS + tid];
#pragma unroll 2
        for (int win = 0; win < WPB; win++) {
            const ulonglong2* fr = reinterpret_cast<const ulonglong2*>(sm + OFF_PRJ + win * 64);
            ull a0 = pack2(bias, 0.f), a1 = 0ull, a2 = 0ull, a3 = 0ull;
#pragma unroll
            for (int q = 0; q < 16; q++) {
                ulonglong2 fv = fr[q];
                if ((q & 1) == 0) { fma2(a0, wv[2 * q], fv.x); fma2(a1, wv[2 * q + 1], fv.y); }
                else              { fma2(a2, wv[2 * q], fv.x); fma2(a3, wv[2 * q + 1], fv.y); }
            }
            add2(a0, a0, a2);
            add2(a1, a1, a3);
            add2(a0, a0, a1);
            g_xg[(wbase + win) * NG + tid] = hsum2(a0);
        }
    }

    // ---- publish chunk ----
    __syncthreads();
    if (tid == 0) {
        __threadfence();
        atomicExch(&g_flag[b * NCHUNK + tc], 1);
    }
}

// ---------------------------------------------------------------------------
extern "C" void kernel_launch(void* const* d_in, const int* in_sizes, int n_in,
                              void* d_out, int out_size) {
    const float* pressure = (const float*)d_in[0];
    const float* torque   = (const float*)d_in[1];
    const float* frag     = (const float*)d_in[2];
    const float* pw1 = (const float*)d_in[3];
    const float* pb1 = (const float*)d_in[4];
    const float* pw2 = (const float*)d_in[5];
    const float* pb2 = (const float*)d_in[6];
    const float* tw1 = (const float*)d_in[7];
    const float* tb1 = (const float*)d_in[8];
    const float* tw2 = (const float*)d_in[9];
    const float* tb2 = (const float*)d_in[10];
    const float* fw  = (const float*)d_in[11];
    const float* fb  = (const float*)d_in[12];
    const float* prw = (const float*)d_in[13];
    const float* prb = (const float*)d_in[14];
    const float* Wih = (const float*)d_in[15];
    const float* Whh = (const float*)d_in[16];
    const float* bih = (const float*)d_in[17];
    const float* bhh = (const float*)d_in[18];
    const float* hw  = (const float*)d_in[19];
    const float* hb  = (const float*)d_in[20];

    static bool attr_set = false;
    if (!attr_set) {
        cudaFuncSetAttribute(fused_kernel, cudaFuncAttributeMaxDynamicSharedMemorySize,
                             SMEM_BYTES);
        attr_set = true;
    }

    fused_kernel<<<64 + NWIN / WPB, 256, SMEM_BYTES>>>(
        pressure, torque, frag,
        pw1, pb1, pw2, pb2, tw1, tb1, tw2, tb2,
        fw, fb, prw, prb, Wih, bih, bhh, Whh, hw, hb, (float*)d_out);
}

// round 16
// speedup vs baseline: 1.5349x; 1.4657x over previous
#include <cuda_runtime.h>

#define DEVINL __device__ __forceinline__
typedef unsigned long long ull;

constexpr int B = 64, T = 256, W = 20, NP = 6, NT = 12, CC = 32, FD = 8, PROJ = 64;
constexpr int NG = 4 * PROJ;            // 256 gates
constexpr int NWIN = B * T;             // 16384
constexpr int WPB = 16;                 // windows per enc block (2 per warp)
constexpr int NCHUNK = 16;              // t-chunks per batch row

// scratch
__device__ float g_xg[NWIN * NG];       // 16 MB: xg = feat @ Wih^T + (bih+bhh)
__device__ int   g_flag[B * NCHUNK];    // chunk flags (self-resetting, start 0)

DEVINL void fma2(ull& d, ull a, ull b) {
    asm("fma.rn.f32x2 %0, %1, %2, %0;" : "+l"(d) : "l"(a), "l"(b));
}
DEVINL void add2(ull& d, ull a, ull b) {
    asm("add.rn.f32x2 %0, %1, %2;" : "=l"(d) : "l"(a), "l"(b));
}
DEVINL float hsum2(ull a) {
    float lo, hi;
    asm("mov.b64 {%0,%1}, %2;" : "=f"(lo), "=f"(hi) : "l"(a));
    return lo + hi;
}
DEVINL ull pack2(float lo, float hi) {
    ull r;
    asm("mov.b64 %0, {%1,%2};" : "=l"(r) : "f"(lo), "f"(hi));
    return r;
}
DEVINL void upk(ull a, float& lo, float& hi) {
    asm("mov.b64 {%0,%1}, %2;" : "=f"(lo), "=f"(hi) : "l"(a));
}

DEVINL float sigm(float x) { return __fdividef(1.f, 1.f + __expf(-x)); }
DEVINL float tanh_(float x) { return __fdividef(2.f, 1.f + __expf(-2.f * x)) - 1.f; }

// ---------------------------------------------------------------------------
// smem layout (floats) — dynamic shared (enc role); r12 + doubled CAT
// ---------------------------------------------------------------------------
constexpr int OFF_W1P  = 0;                       // 576
constexpr int OFF_W1T  = OFF_W1P + 576;           // 1152
constexpr int OFF_W2P  = OFF_W1T + 1152;          // 3072
constexpr int OFF_W2T  = OFF_W2P + 3072;          // 3072
constexpr int OFF_B1P  = OFF_W2T + 3072;          // 32
constexpr int OFF_B1T  = OFF_B1P + 32;            // 32
constexpr int OFF_B2P  = OFF_B1T + 32;            // 32
constexpr int OFF_B2T  = OFF_B2P + 32;            // 32
constexpr int OFF_BIAS = OFF_B2T + 32;            // 256
constexpr int OFF_XP   = OFF_BIAS + 256;          // 8 * 128
constexpr int OFF_XT   = OFF_XP + 8 * 128;        // 8 * 256
constexpr int OFF_H1   = OFF_XT + 8 * 256;        // 8 * 576
constexpr int OFF_CAT  = OFF_H1 + 8 * 576;        // 8 * 160 (two windows/warp)
constexpr int OFF_PRJ  = OFF_CAT + 8 * 160;       // 16 * 64
constexpr int OFF_PRW  = OFF_PRJ + 16 * 64;       // 4608
constexpr int SMEM_FLOATS = OFF_PRW + 4608;       // 22848
constexpr int SMEM_BYTES = SMEM_FLOATS * 4;       // 91392 B -> 2 blocks/SM

// ---------------------------------------------------------------------------
// conv helpers (unchanged from r12)
// ---------------------------------------------------------------------------
template <int NPAIR, int STRIDE>
DEVINL void conv1P(const float* __restrict__ s_x, const float* __restrict__ s_w,
                   float bv, float* __restrict__ h1T) {
    ull acc[18];
#pragma unroll
    for (int j = 0; j < 18; j++) acc[j] = 0ull;
#pragma unroll
    for (int m = 0; m < NPAIR; m++) {
        ull w0 = *reinterpret_cast<const ull*>(s_w + (3 * m + 0) * 64);
        ull w1 = *reinterpret_cast<const ull*>(s_w + (3 * m + 1) * 64);
        ull w2 = *reinterpret_cast<const ull*>(s_w + (3 * m + 2) * 64);
#pragma unroll
        for (int j = 0; j < 20; j++) {
            ull v = *reinterpret_cast<const ull*>(s_x + j * STRIDE + 2 * m);
            if (j < 18) fma2(acc[j], v, w0);
            if (j >= 1 && j <= 18) fma2(acc[j - 1], v, w1);
            if (j >= 2) fma2(acc[j - 2], v, w2);
        }
    }
#pragma unroll
    for (int j = 0; j < 18; j++)
        h1T[j * 32] = fmaxf(hsum2(acc[j]) + bv, 0.f);
}

template <int NQUAD, int STRIDE>
DEVINL void conv1Q(const float* __restrict__ s_x, const float* __restrict__ s_w,
                   float bv, float* __restrict__ h1T) {
    ull acc[18];
#pragma unroll
    for (int j = 0; j < 18; j++) acc[j] = 0ull;
#pragma unroll
    for (int mm = 0; mm < NQUAD; mm++) {
        ulonglong2 w0 = *reinterpret_cast<const ulonglong2*>(s_w + (3 * mm + 0) * 128);
        ulonglong2 w1 = *reinterpret_cast<const ulonglong2*>(s_w + (3 * mm + 1) * 128);
        ulonglong2 w2 = *reinterpret_cast<const ulonglong2*>(s_w + (3 * mm + 2) * 128);
#pragma unroll
        for (int j = 0; j < 20; j++) {
            ulonglong2 v = *reinterpret_cast<const ulonglong2*>(s_x + j * STRIDE + 4 * mm);
            if (j < 18)            { fma2(acc[j], v.x, w0.x);     fma2(acc[j], v.y, w0.y); }
            if (j >= 1 && j <= 18) { fma2(acc[j - 1], v.x, w1.x); fma2(acc[j - 1], v.y, w1.y); }
            if (j >= 2)            { fma2(acc[j - 2], v.x, w2.x); fma2(acc[j - 2], v.y, w2.y); }
        }
    }
#pragma unroll
    for (int j = 0; j < 18; j++)
        h1T[j * 32] = fmaxf(hsum2(acc[j]) + bv, 0.f);
}

DEVINL float conv2Q(const float* __restrict__ h1T, const float* __restrict__ s_w,
                    float bv) {
    ull acc[16];
#pragma unroll
    for (int j = 0; j < 16; j++) acc[j] = 0ull;
#pragma unroll 2
    for (int mm = 0; mm < 8; mm++) {
        ulonglong2 w0 = *reinterpret_cast<const ulonglong2*>(s_w + (3 * mm + 0) * 128);
        ulonglong2 w1 = *reinterpret_cast<const ulonglong2*>(s_w + (3 * mm + 1) * 128);
        ulonglong2 w2 = *reinterpret_cast<const ulonglong2*>(s_w + (3 * mm + 2) * 128);
#pragma unroll
        for (int j = 0; j < 18; j++) {
            ulonglong2 v = *reinterpret_cast<const ulonglong2*>(h1T + j * 32 + 4 * mm);
            if (j < 16)            { fma2(acc[j], v.x, w0.x);     fma2(acc[j], v.y, w0.y); }
            if (j >= 1 && j <= 16) { fma2(acc[j - 1], v.x, w1.x); fma2(acc[j - 1], v.y, w1.y); }
            if (j >= 2)            { fma2(acc[j - 2], v.x, w2.x); fma2(acc[j - 2], v.y, w2.y); }
        }
    }
    float s = 0.f;
#pragma unroll
    for (int j = 0; j < 16; j++)
        s += fmaxf(hsum2(acc[j]) + bv, 0.f);
    return s * (1.f / 16.f);
}

// ---------------------------------------------------------------------------
// Fused kernel. Blocks 0..63: LSTM+head role. Blocks 64..1087: enc role.
// ---------------------------------------------------------------------------
__global__ void __launch_bounds__(256) fused_kernel(
    const float* __restrict__ pressure, const float* __restrict__ torque,
    const float* __restrict__ frag,
    const float* __restrict__ pw1, const float* __restrict__ pb1,
    const float* __restrict__ pw2, const float* __restrict__ pb2,
    const float* __restrict__ tw1, const float* __restrict__ tb1,
    const float* __restrict__ tw2, const float* __restrict__ tb2,
    const float* __restrict__ fw, const float* __restrict__ fb,
    const float* __restrict__ prw, const float* __restrict__ prb,
    const float* __restrict__ Wih, const float* __restrict__ bih,
    const float* __restrict__ bhh, const float* __restrict__ Whh,
    const float* __restrict__ hw, const float* __restrict__ hb,
    float* __restrict__ out) {
    extern __shared__ float sm[];
    const int tid = threadIdx.x;

    if (blockIdx.x < 64) {
        // =================== LSTM + head role (r12, unchanged) ===================
        __shared__ __align__(16) float s_h[PROJ];
        __shared__ float s_gact[NG];
        __shared__ __align__(16) float s_hw[4 * PROJ];
        __shared__ float s_hb[4];
        __shared__ __align__(16) float s_hbuf[16 * PROJ];

        const int b = blockIdx.x;
        const int cls = tid >> 6;  // 0:i 1:f 2:g 3:o

        ull wreg[PROJ / 2];
        {
            const ulonglong2* w2 = reinterpret_cast<const ulonglong2*>(Whh + tid * PROJ);
#pragma unroll
            for (int q = 0; q < PROJ / 4; q++) {
                ulonglong2 v = w2[q];
                wreg[2 * q] = v.x;
                wreg[2 * q + 1] = v.y;
            }
        }

        s_hw[tid] = hw[tid];
        if (tid < 4) s_hb[tid] = hb[tid];
        if (tid < PROJ) s_h[tid] = 0.f;
        float c = 0.f;

        const float* xg = g_xg + b * T * NG;
        __syncthreads();

        for (int ch = 0; ch < NCHUNK; ch++) {
            if (tid == 0) {
                int* fp = &g_flag[b * NCHUNK + ch];
                while (atomicAdd(fp, 0) == 0) { }
                atomicExch(fp, 0);
            }
            __syncthreads();

            float xnext = xg[(ch * 16) * NG + tid];
#pragma unroll 1
            for (int tt = 0; tt < 16; tt++) {
                float xcur = xnext;
                if (tt < 15) xnext = xg[(ch * 16 + tt + 1) * NG + tid];

                ull a[8];
                a[0] = pack2(xcur, 0.f);
#pragma unroll
                for (int i = 1; i < 8; i++) a[i] = 0ull;
                const ulonglong2* h2 = reinterpret_cast<const ulonglong2*>(s_h);
#pragma unroll
                for (int q = 0; q < 16; q++) {
                    ulonglong2 hv = h2[q];
                    fma2(a[(2 * q) & 7], wreg[2 * q], hv.x);
                    fma2(a[(2 * q + 1) & 7], wreg[2 * q + 1], hv.y);
                }
                add2(a[0], a[0], a[4]);
                add2(a[1], a[1], a[5]);
                add2(a[2], a[2], a[6]);
                add2(a[3], a[3], a[7]);
                add2(a[0], a[0], a[2]);
                add2(a[1], a[1], a[3]);
                add2(a[0], a[0], a[1]);
                float g = hsum2(a[0]);
                s_gact[tid] = (cls == 2) ? tanh_(g) : sigm(g);
                __syncthreads();

                if (tid < PROJ) {
                    float ai = s_gact[tid];
                    float af = s_gact[PROJ + tid];
                    float ag = s_gact[2 * PROJ + tid];
                    float ao = s_gact[3 * PROJ + tid];
                    c = fmaf(af, c, ai * ag);
                    float h = ao * tanh_(c);
                    s_h[tid] = h;
                    s_hbuf[tt * PROJ + tid] = h;
                }
                __syncthreads();
            }

            // ---- head for this chunk: 64 outputs, 4 threads each ----
            {
                int tt = tid >> 4, m = (tid >> 2) & 3, part = tid & 3;
                const float* hv = s_hbuf + tt * PROJ + part * 16;
                const float* wv = s_hw + m * PROJ + part * 16;
                float acc = (part == 0) ? s_hb[m] : 0.f;
#pragma unroll
                for (int j = 0; j < 16; j++) acc = fmaf(wv[j], hv[j], acc);
                acc += __shfl_xor_sync(0xffffffffu, acc, 1);
                acc += __shfl_xor_sync(0xffffffffu, acc, 2);
                if (part == 0)
                    out[(b * T + ch * 16 + tt) * 4 + m] = sigm(acc);
            }
        }

        if (tid < PROJ) {
            out[B * T * 4 + b * PROJ + tid] = s_h[tid];             // hT
            out[B * T * 4 + B * PROJ + b * PROJ + tid] = c;         // cT
        }
        return;
    }

    // ======================= Encoder role (r12 + dual-window proj) =======================
    const int k = blockIdx.x - 64;
    const int b = k & 63;
    const int tc = k >> 6;
    const int lane = tid & 31;
    const int warp = tid >> 5;

    // ---- stage weights ----
    for (int t = tid; t < 32 * 3 * 3; t += 256) {         // conv1p pairs
        int o = t / 9, rem = t % 9, m = rem / 3, kk = rem % 3;
        int di = OFF_W1P + (3 * m + kk) * 64 + 2 * o;
        sm[di]     = pw1[(o * NP + 2 * m) * 3 + kk];
        sm[di + 1] = pw1[(o * NP + 2 * m + 1) * 3 + kk];
    }
    for (int t = tid; t < 32 * 3 * 3; t += 256) {         // conv1t quads
        int o = t / 9, rem = t % 9, mm = rem / 3, kk = rem % 3;
        int di = OFF_W1T + (3 * mm + kk) * 128 + 4 * o;
#pragma unroll
        for (int q = 0; q < 4; q++)
            sm[di + q] = tw1[(o * NT + 4 * mm + q) * 3 + kk];
    }
    for (int t = tid; t < 32 * 8 * 3; t += 256) {         // conv2 quads
        int o = t / 24, rem = t % 24, mm = rem / 3, kk = rem % 3;
        int di = (3 * mm + kk) * 128 + 4 * o;
#pragma unroll
        for (int q = 0; q < 4; q++) {
            int si = (o * CC + 4 * mm + q) * 3 + kk;
            sm[OFF_W2P + di + q] = pw2[si];
            sm[OFF_W2T + di + q] = tw2[si];
        }
    }
    for (int t = tid; t < 36 * 32; t += 256) {            // prwT quad-pack
        int q = t >> 5, o = t & 31;
        int di = OFF_PRW + q * 128 + o * 4;
        sm[di + 0] = prw[o * 72 + 2 * q];
        sm[di + 1] = prw[(o + 32) * 72 + 2 * q];
        sm[di + 2] = prw[o * 72 + 2 * q + 1];
        sm[di + 3] = prw[(o + 32) * 72 + 2 * q + 1];
    }
    if (tid < 32) {
        sm[OFF_B1P + tid] = pb1[tid]; sm[OFF_B1T + tid] = tb1[tid];
        sm[OFF_B2P + tid] = pb2[tid]; sm[OFF_B2T + tid] = tb2[tid];
    }
    sm[OFF_BIAS + tid] = bih[tid] + bhh[tid];
    __syncthreads();

    const int wbase = b * 256 + tc * 16;   // wi = wbase + win, win = 0..15

    float* sxp = sm + OFF_XP + warp * 128;
    float* sxt = sm + OFF_XT + warp * 256;
    float* sh1 = sm + OFF_H1 + warp * 576;
    float* sftA = sm + OFF_CAT + warp * 160;
    float* sftB = sftA + 80;

#pragma unroll 1
    for (int w2 = 0; w2 < 2; w2++) {
        const int wi = wbase + warp * 2 + w2;
        float* sft = (w2 == 0) ? sftA : sftB;

        // ---- load window inputs (raw [pos][ch] layout kept) ----
        {
            const float4* gp4 = reinterpret_cast<const float4*>(pressure + wi * 120);
            if (lane < 30) reinterpret_cast<float4*>(sxp)[lane] = gp4[lane];
            const float4* gt4 = reinterpret_cast<const float4*>(torque + wi * 240);
            reinterpret_cast<float4*>(sxt)[lane] = gt4[lane];
            if (lane < 28) reinterpret_cast<float4*>(sxt)[lane + 32] = gt4[lane + 32];
        }
        __syncwarp();

        // ---- pressure: conv1 -> h1T -> conv2 -> pooled ----
        conv1P<3, NP>(sxp, sm + OFF_W1P + 2 * lane, sm[OFF_B1P + lane], sh1 + lane);
        __syncwarp();
        float poolp = conv2Q(sh1, sm + OFF_W2P + 4 * lane, sm[OFF_B2P + lane]);
        __syncwarp();

        // ---- torque: conv1 -> h1T -> conv2 -> pooled ----
        conv1Q<3, NT>(sxt, sm + OFF_W1T + 4 * lane, sm[OFF_B1T + lane], sh1 + lane);
        __syncwarp();
        float poolt = conv2Q(sh1, sm + OFF_W2T + 4 * lane, sm[OFF_B2T + lane]);

        sft[lane] = poolp;
        sft[32 + lane] = poolt;
        if (lane < FD) sft[64 + lane] = fmaxf(fmaf(frag[b], fw[lane], fb[lane]), 0.f);
        __syncwarp();
    }

    // ---- DUAL projection: one prwT fetch feeds both windows ----
    {
        float* spjA = sm + OFF_PRJ + (warp * 2) * 64;
        float* spjB = spjA + 64;
        ull aA = 0ull, bA = 0ull, aB = 0ull, bB = 0ull;
        const float* sw = sm + OFF_PRW + 4 * lane;
#pragma unroll
        for (int q = 0; q < 36; q++) {
            ulonglong2 wq = *reinterpret_cast<const ulonglong2*>(sw + q * 128);
            ull xpa = *reinterpret_cast<const ull*>(sftA + 2 * q);
            ull xpb = *reinterpret_cast<const ull*>(sftB + 2 * q);
            float a0, a1, b0, b1;
            upk(xpa, a0, a1);
            upk(xpb, b0, b1);
            fma2(aA, wq.x, pack2(a0, a0));
            fma2(bA, wq.y, pack2(a1, a1));
            fma2(aB, wq.x, pack2(b0, b0));
            fma2(bB, wq.y, pack2(b1, b1));
        }
        add2(aA, aA, bA);
        add2(aB, aB, bB);
        float loA, hiA, loB, hiB;
        upk(aA, loA, hiA);
        upk(aB, loB, hiB);
        float pb0 = prb[lane], pb32 = prb[lane + 32];
        spjA[lane]      = fmaxf(loA + pb0, 0.f);
        spjA[lane + 32] = fmaxf(hiA + pb32, 0.f);
        spjB[lane]      = fmaxf(loB + pb0, 0.f);
        spjB[lane + 32] = fmaxf(hiB + pb32, 0.f);
    }
    __syncthreads();

    // ---- xg: gate tid for all 16 windows; Wih row held in registers ----
    {
        ull wv[32];
        const ulonglong2* wr = reinterpret_cast<const ulonglong2*>(Wih + tid * PROJ);
#pragma unroll
        for (int q = 0; q < 16; q++) {
            ulonglong2 v = wr[q];
            wv[2 * q] = v.x; wv[2 * q + 1] = v.y;
        }
        float bias = sm[OFF_BIAS + tid];
#pragma unroll 2
        for (int win = 0; win < WPB; win++) {
            const ulonglong2* fr = reinterpret_cast<const ulonglong2*>(sm + OFF_PRJ + win * 64);
            ull a0 = pack2(bias, 0.f), a1 = 0ull, a2 = 0ull, a3 = 0ull;
#pragma unroll
            for (int q = 0; q < 16; q++) {
                ulonglong2 fv = fr[q];
                if ((q & 1) == 0) { fma2(a0, wv[2 * q], fv.x); fma2(a1, wv[2 * q + 1], fv.y); }
                else              { fma2(a2, wv[2 * q], fv.x); fma2(a3, wv[2 * q + 1], fv.y); }
            }
            add2(a0, a0, a2);
            add2(a1, a1, a3);
            add2(a0, a0, a1);
            g_xg[(wbase + win) * NG + tid] = hsum2(a0);
        }
    }

    // ---- publish chunk ----
    __syncthreads();
    if (tid == 0) {
        __threadfence();
        atomicExch(&g_flag[b * NCHUNK + tc], 1);
    }
}

// ---------------------------------------------------------------------------
extern "C" void kernel_launch(void* const* d_in, const int* in_sizes, int n_in,
                              void* d_out, int out_size) {
    const float* pressure = (const float*)d_in[0];
    const float* torque   = (const float*)d_in[1];
    const float* frag     = (const float*)d_in[2];
    const float* pw1 = (const float*)d_in[3];
    const float* pb1 = (const float*)d_in[4];
    const float* pw2 = (const float*)d_in[5];
    const float* pb2 = (const float*)d_in[6];
    const float* tw1 = (const float*)d_in[7];
    const float* tb1 = (const float*)d_in[8];
    const float* tw2 = (const float*)d_in[9];
    const float* tb2 = (const float*)d_in[10];
    const float* fw  = (const float*)d_in[11];
    const float* fb  = (const float*)d_in[12];
    const float* prw = (const float*)d_in[13];
    const float* prb = (const float*)d_in[14];
    const float* Wih = (const float*)d_in[15];
    const float* Whh = (const float*)d_in[16];
    const float* bih = (const float*)d_in[17];
    const float* bhh = (const float*)d_in[18];
    const float* hw  = (const float*)d_in[19];
    const float* hb  = (const float*)d_in[20];

    static bool attr_set = false;
    if (!attr_set) {
        cudaFuncSetAttribute(fused_kernel, cudaFuncAttributeMaxDynamicSharedMemorySize,
                             SMEM_BYTES);
        attr_set = true;
    }

    fused_kernel<<<64 + NWIN / WPB, 256, SMEM_BYTES>>>(
        pressure, torque, frag,
        pw1, pb1, pw2, pb2, tw1, tb1, tw2, tb2,
        fw, fb, prw, prb, Wih, bih, bhh, Whh, hw, hb, (float*)d_out);
}